// round 1
// baseline (speedup 1.0000x reference)
#include <cuda_runtime.h>
#include <cuda_bf16.h>
#include <math.h>

// ---------------------------------------------------------------------------
// Problem constants
//   x: [16,128,128,128]  conv2x2/s2 -> [16,128,64,64]
//   windows: P=4, yg=xg=16, tokens per sample = 256*16 = 4096, total T=65536
//   C=128, heads=2, hd=64, attn scale = 1/sqrt(128)
// ---------------------------------------------------------------------------
#define T_TOK   65536        // total tokens
#define CCH     128
#define NWIN    4096         // 16 * 256 windows
#define NPIX    4096         // 64*64 pixels per sample

// scratch (device globals; no allocation allowed)
__device__ float g_X  [T_TOK * 128];      // token activations  (32MB)
__device__ float g_QKV[T_TOK * 384];      // qkv buffer         (96MB)
__device__ float g_Hid[(size_t)T_TOK * 512]; // mlp hidden      (128MB)
__device__ float g_Xr [T_TOK * 128];      // pixel-major reorder(32MB)
__device__ float g_h  [NPIX * 128];
__device__ float g_c  [NPIX * 128];
__device__ float g_gates[NPIX * 512];
__device__ float g_Wt [512 * 128];        // conv weight, im2col-transposed
__device__ float g_Wl [512 * 256];        // [Wx | Wh] combined

// ---------------------------------------------------------------------------
// prep kernels
// ---------------------------------------------------------------------------
__global__ void prep_convw(const float* __restrict__ cw, float* __restrict__ Wt) {
    int idx = blockIdx.x * 128 + threadIdx.x;      // 65536
    int k = idx >> 7, o = idx & 127;               // k = i*4 + ky*2 + kx
    Wt[idx] = cw[o * 512 + k];
}

__global__ void prep_lstmw(const float* __restrict__ wx, const float* __restrict__ wh,
                           float* __restrict__ Wl) {
    int idx = blockIdx.x * 128 + threadIdx.x;      // 131072
    int o = idx >> 8, k = idx & 255;
    Wl[idx] = (k < 128) ? wx[o * 128 + k] : wh[o * 128 + (k - 128)];
}

__global__ void init_hc(const float* __restrict__ h0, const float* __restrict__ c0,
                        float* __restrict__ h, float* __restrict__ c) {
    int idx = blockIdx.x * 128 + threadIdx.x;      // 524288, idx = ch*4096 + p
    int ch = idx >> 12, p = idx & 4095;
    h[p * 128 + ch] = h0[idx];
    c[p * 128 + ch] = c0[idx];
}

// ---------------------------------------------------------------------------
// conv 2x2 stride 2 + window partition, output token-major [t][o]
// block = one window (b,yg,xg), 128 threads = out channels
// ---------------------------------------------------------------------------
__global__ void conv_kernel(const float* __restrict__ x, const float* __restrict__ Wt,
                            const float* __restrict__ bias, float* __restrict__ X) {
    __shared__ float xs[128 * 64];  // [i][r(8)][cc(8)] for the 8x8 input patch
    int w = blockIdx.x;                       // 4096
    int b = w >> 8, yg = (w >> 4) & 15, xg = w & 15;
    int o = threadIdx.x;

    for (int idx = o; idx < 8192; idx += 128) {
        int i = idx >> 6, r = (idx >> 3) & 7, cc = idx & 7;
        xs[idx] = x[((size_t)(b * 128 + i) * 128 + (yg * 8 + r)) * 128 + (xg * 8 + cc)];
    }
    __syncthreads();

    float acc[16];
    float bv = bias[o];
#pragma unroll
    for (int t = 0; t < 16; t++) acc[t] = bv;

    for (int k = 0; k < 512; k++) {
        int i = k >> 2, ky = (k >> 1) & 1, kx = k & 1;
        float wv = Wt[k * 128 + o];
        int base = i * 64 + ky * 8 + kx;
#pragma unroll
        for (int t = 0; t < 16; t++) {
            int off = (t >> 2) * 16 + (t & 3) * 2;
            acc[t] = fmaf(wv, xs[base + off], acc[t]);
        }
    }
    int tokbase = w * 16;
#pragma unroll
    for (int t = 0; t < 16; t++)
        X[(size_t)(tokbase + t) * 128 + o] = acc[t];
}

// ---------------------------------------------------------------------------
// generic NT SGEMM:  C[M,N] = A[M,K] * W[N,K]^T  (+bias)(+gelu)(+residual)
// BM=128 BN=64 BK=16, 256 threads, 8x4 microtile.
// EPI: 0 = bias, 1 = bias+exact GELU, 2 = bias + residual R
// M%128==0, N%64==0, K%16==0 guaranteed.
// ---------------------------------------------------------------------------
__device__ __forceinline__ float gelu_exact(float v) {
    return 0.5f * v * (1.0f + erff(v * 0.70710678118654752f));
}

template<int EPI>
__global__ void __launch_bounds__(256) gemm_nt(
        const float* __restrict__ A, const float* __restrict__ W,
        const float* __restrict__ bias, const float* __restrict__ R,
        float* __restrict__ C, int M, int N, int K) {
    __shared__ __align__(16) float As[16][136];
    __shared__ __align__(16) float Ws[16][72];
    const int tid = threadIdx.x;
    const int bm = blockIdx.y * 128, bn = blockIdx.x * 64;
    const int tx = tid & 15, ty = tid >> 4;

    float acc[8][4];
#pragma unroll
    for (int i = 0; i < 8; i++)
#pragma unroll
        for (int j = 0; j < 4; j++) acc[i][j] = 0.f;

    for (int k0 = 0; k0 < K; k0 += 16) {
#pragma unroll
        for (int i = 0; i < 8; i++) {
            int idx = tid + i * 256;              // 2048 = 128x16
            int m = idx >> 4, k = idx & 15;
            As[k][m] = A[(size_t)(bm + m) * K + k0 + k];
        }
#pragma unroll
        for (int i = 0; i < 4; i++) {
            int idx = tid + i * 256;              // 1024 = 64x16
            int m = idx >> 4, k = idx & 15;
            Ws[k][m] = W[(size_t)(bn + m) * K + k0 + k];
        }
        __syncthreads();
#pragma unroll
        for (int k = 0; k < 16; k++) {
            float4 a0 = *(const float4*)&As[k][ty * 8];
            float4 a1 = *(const float4*)&As[k][ty * 8 + 4];
            float4 w0 = *(const float4*)&Ws[k][tx * 4];
            float a[8] = {a0.x, a0.y, a0.z, a0.w, a1.x, a1.y, a1.z, a1.w};
            float wv[4] = {w0.x, w0.y, w0.z, w0.w};
#pragma unroll
            for (int i = 0; i < 8; i++)
#pragma unroll
                for (int j = 0; j < 4; j++)
                    acc[i][j] = fmaf(a[i], wv[j], acc[i][j]);
        }
        __syncthreads();
    }

#pragma unroll
    for (int i = 0; i < 8; i++) {
        int m = bm + ty * 8 + i;
        size_t off = (size_t)m * N + bn + tx * 4;
        float4 v;
        float* vp = &v.x;
#pragma unroll
        for (int j = 0; j < 4; j++) {
            int n = bn + tx * 4 + j;
            float t = acc[i][j] + bias[n];
            if (EPI == 1) t = gelu_exact(t);
            vp[j] = t;
        }
        if (EPI == 2) {
            float4 r = *(const float4*)&R[off];
            v.x += r.x; v.y += r.y; v.z += r.z; v.w += r.w;
        }
        *(float4*)&C[off] = v;
    }
}

// ---------------------------------------------------------------------------
// LSTM gates GEMM: gates[4096,512] = [Xn | h][4096,256] * Wl[512,256]^T + b
// ---------------------------------------------------------------------------
__global__ void __launch_bounds__(256) gemm_lstm(
        const float* __restrict__ Xn, const float* __restrict__ Hh,
        const float* __restrict__ Wl, const float* __restrict__ bias,
        float* __restrict__ C) {
    const int M = 4096, N = 512, K = 256;
    __shared__ __align__(16) float As[16][136];
    __shared__ __align__(16) float Ws[16][72];
    const int tid = threadIdx.x;
    const int bm = blockIdx.y * 128, bn = blockIdx.x * 64;
    const int tx = tid & 15, ty = tid >> 4;

    float acc[8][4];
#pragma unroll
    for (int i = 0; i < 8; i++)
#pragma unroll
        for (int j = 0; j < 4; j++) acc[i][j] = 0.f;

    for (int k0 = 0; k0 < K; k0 += 16) {
#pragma unroll
        for (int i = 0; i < 8; i++) {
            int idx = tid + i * 256;
            int m = idx >> 4, k = idx & 15;
            int kg = k0 + k;
            As[k][m] = (kg < 128) ? Xn[(bm + m) * 128 + kg]
                                  : Hh[(bm + m) * 128 + (kg - 128)];
        }
#pragma unroll
        for (int i = 0; i < 4; i++) {
            int idx = tid + i * 256;
            int m = idx >> 4, k = idx & 15;
            Ws[k][m] = Wl[(bn + m) * K + k0 + k];
        }
        __syncthreads();
#pragma unroll
        for (int k = 0; k < 16; k++) {
            float4 a0 = *(const float4*)&As[k][ty * 8];
            float4 a1 = *(const float4*)&As[k][ty * 8 + 4];
            float4 w0 = *(const float4*)&Ws[k][tx * 4];
            float a[8] = {a0.x, a0.y, a0.z, a0.w, a1.x, a1.y, a1.z, a1.w};
            float wv[4] = {w0.x, w0.y, w0.z, w0.w};
#pragma unroll
            for (int i = 0; i < 8; i++)
#pragma unroll
                for (int j = 0; j < 4; j++)
                    acc[i][j] = fmaf(a[i], wv[j], acc[i][j]);
        }
        __syncthreads();
    }
#pragma unroll
    for (int i = 0; i < 8; i++) {
        int m = bm + ty * 8 + i;
        size_t off = (size_t)m * N + bn + tx * 4;
        float4 v;
        float* vp = &v.x;
#pragma unroll
        for (int j = 0; j < 4; j++) vp[j] = acc[i][j] + bias[bn + tx * 4 + j];
        *(float4*)&C[off] = v;
    }
}

// ---------------------------------------------------------------------------
// attention 1: per window (16 tokens, 2 heads, hd=64). X += attn(V)
// ---------------------------------------------------------------------------
__global__ void attn1_kernel(const float* __restrict__ QKV, float* __restrict__ X) {
    __shared__ float q[16][384];
    __shared__ float s[2][16][16];
    int w = blockIdx.x, tid = threadIdx.x;   // 128 threads
    size_t base = (size_t)w * 16 * 384;
    for (int i = tid; i < 16 * 384; i += 128) q[i / 384][i % 384] = QKV[base + i];
    __syncthreads();

    for (int idx = tid; idx < 512; idx += 128) {
        int h = idx >> 8, t1 = (idx >> 4) & 15, t2 = idx & 15;
        const float* qp = &q[t1][h * 64];
        const float* kp = &q[t2][128 + h * 64];
        float a = 0.f;
#pragma unroll
        for (int c = 0; c < 64; c++) a = fmaf(qp[c], kp[c], a);
        s[h][t1][t2] = a * 0.08838834764831843f;
    }
    __syncthreads();
    if (tid < 32) {
        int h = tid >> 4, t1 = tid & 15;
        float m = -1e30f;
#pragma unroll
        for (int j = 0; j < 16; j++) m = fmaxf(m, s[h][t1][j]);
        float sum = 0.f;
#pragma unroll
        for (int j = 0; j < 16; j++) { float e = expf(s[h][t1][j] - m); s[h][t1][j] = e; sum += e; }
        float inv = 1.f / sum;
#pragma unroll
        for (int j = 0; j < 16; j++) s[h][t1][j] *= inv;
    }
    __syncthreads();
    for (int idx = tid; idx < 2048; idx += 128) {
        int t1 = idx >> 7, ch = idx & 127, h = ch >> 6;
        float a = 0.f;
#pragma unroll
        for (int j = 0; j < 16; j++) a = fmaf(s[h][t1][j], q[j][256 + ch], a);
        X[(size_t)(w * 16 + t1) * 128 + ch] += a;
    }
}

// ---------------------------------------------------------------------------
// attention 2: per (b,l,head) group of 256 tokens; online softmax.
// block = 256 threads, one query per thread. K/V staged in 128KB dyn smem.
// ---------------------------------------------------------------------------
__global__ void __launch_bounds__(256, 1) attn2_kernel(
        const float* __restrict__ QKV, float* __restrict__ X) {
    extern __shared__ __align__(16) float sm[];
    float* Ks = sm;             // [256][64]
    float* Vs = sm + 256 * 64;  // [256][64]
    int blk = blockIdx.x;                 // 512 = (b*16+l)*2 + head
    int head = blk & 1;
    int bl = blk >> 1;
    int b = bl >> 4, l = bl & 15;
    int tid = threadIdx.x;

    for (int i = tid; i < 256 * 64; i += 256) {
        int g = i >> 6, hc = i & 63;
        size_t t = (size_t)(b * 256 + g) * 16 + l;
        Ks[i] = QKV[t * 384 + 128 + head * 64 + hc];
        Vs[i] = QKV[t * 384 + 256 + head * 64 + hc];
    }
    float qv[64];
    {
        size_t t = (size_t)(b * 256 + tid) * 16 + l;
        const float* qp = &QKV[t * 384 + head * 64];
#pragma unroll
        for (int c = 0; c < 64; c++) qv[c] = qp[c];
    }
    __syncthreads();

    float m = -1e30f, lsum = 0.f;
    float acc[64];
#pragma unroll
    for (int c = 0; c < 64; c++) acc[c] = 0.f;

    for (int j = 0; j < 256; j++) {
        const float4* kp = (const float4*)&Ks[j * 64];
        float s = 0.f;
#pragma unroll
        for (int c4 = 0; c4 < 16; c4++) {
            float4 kk = kp[c4];
            s = fmaf(qv[c4 * 4 + 0], kk.x, s);
            s = fmaf(qv[c4 * 4 + 1], kk.y, s);
            s = fmaf(qv[c4 * 4 + 2], kk.z, s);
            s = fmaf(qv[c4 * 4 + 3], kk.w, s);
        }
        s *= 0.08838834764831843f;
        float mn = fmaxf(m, s);
        float corr = expf(m - mn);
        float p = expf(s - mn);
        lsum = lsum * corr + p;
        const float4* vp = (const float4*)&Vs[j * 64];
#pragma unroll
        for (int c4 = 0; c4 < 16; c4++) {
            float4 vv = vp[c4];
            acc[c4 * 4 + 0] = fmaf(acc[c4 * 4 + 0], corr, p * vv.x);
            acc[c4 * 4 + 1] = fmaf(acc[c4 * 4 + 1], corr, p * vv.y);
            acc[c4 * 4 + 2] = fmaf(acc[c4 * 4 + 2], corr, p * vv.z);
            acc[c4 * 4 + 3] = fmaf(acc[c4 * 4 + 3], corr, p * vv.w);
        }
        m = mn;
    }
    float inv = 1.f / lsum;
    size_t t = (size_t)(b * 256 + tid) * 16 + l;
    float* xo = &X[t * 128 + head * 64];
#pragma unroll
    for (int c = 0; c < 64; c++) xo[c] += acc[c] * inv;
}

// ---------------------------------------------------------------------------
// reorder tokens -> pixel-major per sample: Xr[n][p][c]
// ---------------------------------------------------------------------------
__global__ void reorder_kernel(const float* __restrict__ X, float* __restrict__ Xr) {
    int idx = blockIdx.x * 256 + threadIdx.x;      // 8388608
    int n = idx >> 19;
    int r = idx & 524287;
    int p = r >> 7, ch = r & 127;
    int y = p >> 6, xx = p & 63;
    int yg = y >> 2, yl = y & 3, xg = xx >> 2, xl = xx & 3;
    int t = (n * 256 + yg * 16 + xg) * 16 + yl * 4 + xl;
    Xr[idx] = X[(size_t)t * 128 + ch];
}

// ---------------------------------------------------------------------------
// LSTM pointwise: channel softmaxes + state update + outputs
// block = one pixel, 128 threads = channels
// ---------------------------------------------------------------------------
__device__ __forceinline__ float softmax128(float v, float* red) {
    const unsigned FULL = 0xffffffffu;
    float m = v;
#pragma unroll
    for (int o = 16; o; o >>= 1) m = fmaxf(m, __shfl_xor_sync(FULL, m, o));
    if ((threadIdx.x & 31) == 0) red[threadIdx.x >> 5] = m;
    __syncthreads();
    m = fmaxf(fmaxf(red[0], red[1]), fmaxf(red[2], red[3]));
    __syncthreads();
    float e = expf(v - m), s = e;
#pragma unroll
    for (int o = 16; o; o >>= 1) s += __shfl_xor_sync(FULL, s, o);
    if ((threadIdx.x & 31) == 0) red[threadIdx.x >> 5] = s;
    __syncthreads();
    s = red[0] + red[1] + red[2] + red[3];
    __syncthreads();
    return e / s;
}

__global__ void lstm_point(const float* __restrict__ gates, float* __restrict__ h,
                           float* __restrict__ cst, float* __restrict__ out, int n) {
    __shared__ float red[4];
    int p = blockIdx.x, tid = threadIdx.x;
    float f  = gates[p * 512 + tid];
    float ig = gates[p * 512 + 128 + tid];
    float s  = gates[p * 512 + 256 + tid];
    float o  = gates[p * 512 + 384 + tid];
    f  = softmax128(f,  red);
    ig = softmax128(ig, red);
    o  = softmax128(o,  red);
    float cc = cst[p * 128 + tid];
    float cn = f * cc + ig * tanhf(s);
    float hn = o * tanhf(cn);
    cst[p * 128 + tid] = cn;
    h[p * 128 + tid]   = hn;
    out[((size_t)(n * 128 + tid)) * 4096 + p] = hn;          // hs
    if (n == 15) {
        out[((size_t)(16 * 128 + tid)) * 4096 + p] = hn;     // hf
        out[((size_t)(17 * 128 + tid)) * 4096 + p] = cn;     // Cf
    }
}

// ---------------------------------------------------------------------------
extern "C" void kernel_launch(void* const* d_in, const int* in_sizes, int n_in,
                              void* d_out, int out_size) {
    const float* x       = (const float*)d_in[0];
    const float* h0      = (const float*)d_in[1];
    const float* c0      = (const float*)d_in[2];
    const float* conv_w  = (const float*)d_in[3];
    const float* conv_b  = (const float*)d_in[4];
    const float* qkv1_w  = (const float*)d_in[5];
    const float* qkv1_b  = (const float*)d_in[6];
    const float* mlp1_w1 = (const float*)d_in[7];
    const float* mlp1_b1 = (const float*)d_in[8];
    const float* mlp1_w2 = (const float*)d_in[9];
    const float* mlp1_b2 = (const float*)d_in[10];
    const float* qkv2_w  = (const float*)d_in[11];
    const float* qkv2_b  = (const float*)d_in[12];
    const float* mlp2_w1 = (const float*)d_in[13];
    const float* mlp2_b1 = (const float*)d_in[14];
    const float* mlp2_w2 = (const float*)d_in[15];
    const float* mlp2_b2 = (const float*)d_in[16];
    const float* lstm_wx = (const float*)d_in[17];
    const float* lstm_wh = (const float*)d_in[18];
    const float* lstm_bh = (const float*)d_in[19];
    float* out = (float*)d_out;
    (void)in_sizes; (void)n_in; (void)out_size;

    float *X, *QKV, *Hid, *Xr, *h, *c, *gates, *Wt, *Wl;
    cudaGetSymbolAddress((void**)&X,  g_X);
    cudaGetSymbolAddress((void**)&QKV, g_QKV);
    cudaGetSymbolAddress((void**)&Hid, g_Hid);
    cudaGetSymbolAddress((void**)&Xr, g_Xr);
    cudaGetSymbolAddress((void**)&h,  g_h);
    cudaGetSymbolAddress((void**)&c,  g_c);
    cudaGetSymbolAddress((void**)&gates, g_gates);
    cudaGetSymbolAddress((void**)&Wt, g_Wt);
    cudaGetSymbolAddress((void**)&Wl, g_Wl);

    prep_convw<<<512, 128>>>(conv_w, Wt);
    prep_lstmw<<<1024, 128>>>(lstm_wx, lstm_wh, Wl);
    init_hc<<<4096, 128>>>(h0, c0, h, c);

    // conv + window partition -> X tokens
    conv_kernel<<<NWIN, 128>>>(x, Wt, conv_b, X);

    // LocalMSA
    gemm_nt<0><<<dim3(384 / 64, T_TOK / 128), 256>>>(X, qkv1_w, qkv1_b, nullptr, QKV, T_TOK, 384, 128);
    attn1_kernel<<<NWIN, 128>>>(QKV, X);
    // MLP1
    gemm_nt<1><<<dim3(512 / 64, T_TOK / 128), 256>>>(X, mlp1_w1, mlp1_b1, nullptr, Hid, T_TOK, 512, 128);
    gemm_nt<2><<<dim3(128 / 64, T_TOK / 128), 256>>>(Hid, mlp1_w2, mlp1_b2, X, X, T_TOK, 128, 512);

    // DilatedMSA
    gemm_nt<0><<<dim3(384 / 64, T_TOK / 128), 256>>>(X, qkv2_w, qkv2_b, nullptr, QKV, T_TOK, 384, 128);
    cudaFuncSetAttribute(attn2_kernel, cudaFuncAttributeMaxDynamicSharedMemorySize, 131072);
    attn2_kernel<<<512, 256, 131072>>>(QKV, X);
    // MLP2
    gemm_nt<1><<<dim3(512 / 64, T_TOK / 128), 256>>>(X, mlp2_w1, mlp2_b1, nullptr, Hid, T_TOK, 512, 128);
    gemm_nt<2><<<dim3(128 / 64, T_TOK / 128), 256>>>(Hid, mlp2_w2, mlp2_b2, X, X, T_TOK, 128, 512);

    // window reverse (token -> pixel-major per sample)
    reorder_kernel<<<32768, 256>>>(X, Xr);

    // ConvLSTM scan over 16 samples
    for (int n = 0; n < 16; n++) {
        gemm_lstm<<<dim3(512 / 64, 4096 / 128), 256>>>(Xr + (size_t)n * NPIX * 128, h, Wl, lstm_bh, gates);
        lstm_point<<<NPIX, 128>>>(gates, h, c, out, n);
    }
}

// round 5
// speedup vs baseline: 2.1384x; 2.1384x over previous
#include <cuda_runtime.h>
#include <cuda_bf16.h>
#include <cstdint>
#include <math.h>

// ===========================================================================
// Problem constants
// ===========================================================================
#define T_TOK   65536
#define NWIN    4096
#define NPIX    4096

// scratch (device globals; no allocation allowed)
__device__ float g_X  [T_TOK * 128];
__device__ float g_QKV[T_TOK * 384];
__device__ float g_Hid[(size_t)T_TOK * 512];   // NHWC x / mlp hidden / attn scores S (134MB)
__device__ float g_Xr [T_TOK * 128];
__device__ float g_Vt [512 * 64 * 256];
__device__ float g_h  [NPIX * 128];
__device__ float g_c  [NPIX * 128];
__device__ float g_gates[NPIX * 512];
__device__ float g_Wc [128 * 512];
__device__ float g_Wl [512 * 256];

__device__ __forceinline__ uint32_t f2tf32(float f) {
    uint32_t u; asm("cvt.rna.tf32.f32 %0, %1;" : "=r"(u) : "f"(f)); return u;
}

__device__ __forceinline__ void mma_tf32(float* c, const uint32_t* a, const uint32_t* b) {
    asm volatile(
        "mma.sync.aligned.m16n8k8.row.col.f32.tf32.tf32.f32 "
        "{%0,%1,%2,%3}, {%4,%5,%6,%7}, {%8,%9}, {%0,%1,%2,%3};"
        : "+f"(c[0]), "+f"(c[1]), "+f"(c[2]), "+f"(c[3])
        : "r"(a[0]), "r"(a[1]), "r"(a[2]), "r"(a[3]), "r"(b[0]), "r"(b[1]));
}

// ===========================================================================
// prep kernels
// ===========================================================================
__global__ void prep_convw(const float* __restrict__ cw, float* __restrict__ Wc) {
    int idx = blockIdx.x * 128 + threadIdx.x;  // 65536
    int o = idx >> 9, rem = idx & 511, tap = rem >> 7, i = rem & 127;
    Wc[idx] = cw[o * 512 + i * 4 + tap];
}
__global__ void prep_lstmw(const float* __restrict__ wx, const float* __restrict__ wh,
                           float* __restrict__ Wl) {
    int idx = blockIdx.x * 128 + threadIdx.x;  // 131072
    int o = idx >> 8, k = idx & 255;
    Wl[idx] = (k < 128) ? wx[o * 128 + k] : wh[o * 128 + (k - 128)];
}
__global__ void init_hc(const float* __restrict__ h0, const float* __restrict__ c0,
                        float* __restrict__ h, float* __restrict__ c) {
    int idx = blockIdx.x * 128 + threadIdx.x;  // 524288, idx = ch*4096 + p
    int ch = idx >> 12, p = idx & 4095;
    h[p * 128 + ch] = h0[idx];
    c[p * 128 + ch] = c0[idx];
}

// NCHW -> NHWC transpose of x: xt[(b*128+Y)*16384 + xx*128 + i] = x[b][i][Y][xx]
// OUTPUT REQUIRES 33,554,432 floats -> g_Hid (g_Xr was too small: R4 OOB bug)
__global__ void transpose_x(const float* __restrict__ x, float* __restrict__ xt) {
    __shared__ float t[32][33];
    int bid = blockIdx.x;               // 32768
    int tile = bid & 15, by = bid >> 4;
    int i0 = (tile >> 2) * 32, x0 = (tile & 3) * 32;
    int tx = threadIdx.x & 31, ty = threadIdx.x >> 5;
    const float* xin = x + (size_t)(by >> 7) * 2097152 + (size_t)(by & 127) * 128;
#pragma unroll
    for (int k = 0; k < 4; k++)
        t[ty + k * 8][tx] = xin[(size_t)(i0 + ty + k * 8) * 16384 + x0 + tx];
    __syncthreads();
    float* xout = xt + (size_t)by * 16384;
#pragma unroll
    for (int k = 0; k < 4; k++)
        xout[(size_t)(x0 + ty + k * 8) * 128 + i0 + tx] = t[tx][ty + k * 8];
}

// ===========================================================================
// generic mma.sync tf32 GEMM.  BM=128, BN=NT, BK=32, 256 threads / 8 warps.
// MODE: 0 plain | 1 conv-im2col A | 2 lstm split A | 3 attn QK^T | 4 attn PV
// EPI:  0 bias | 1 bias+gelu | 2 bias+add-to-C | 3 scale-store | 4 add-to-C
// ===========================================================================
template<int MODE>
__device__ __forceinline__ const float* a_ptr(const float* A, const float* A2, int lda,
                                              int m, int k0, int blh) {
    if constexpr (MODE == 1) {
        int w = m >> 4, pl = m & 15;
        int b = w >> 8, yg = (w >> 4) & 15, xg = w & 15;
        int yl = pl >> 2, xl = pl & 3;
        int tap = k0 >> 7, ky = tap >> 1, kx = tap & 1;
        int Y = yg * 8 + yl * 2 + ky, XX = xg * 8 + xl * 2 + kx;
        return A + ((size_t)(b * 128 + Y) * 128 + XX) * 128 + (k0 & 127);
    } else if constexpr (MODE == 2) {
        return (k0 < 128) ? (A + (size_t)m * 128 + k0) : (A2 + (size_t)m * 128 + (k0 - 128));
    } else if constexpr (MODE == 3) {
        int b = blh >> 5, l = (blh >> 1) & 15, h = blh & 1;
        return A + ((size_t)((b * 256 + m) * 16 + l)) * 384 + h * 64 + k0;
    } else if constexpr (MODE == 4) {
        return A + (size_t)blh * 65536 + (size_t)m * 256 + k0;
    } else {
        return A + (size_t)m * lda + k0;
    }
}
template<int MODE>
__device__ __forceinline__ const float* b_ptr(const float* B, int ldb, int n, int k0, int blh) {
    if constexpr (MODE == 3) {
        int b = blh >> 5, l = (blh >> 1) & 15, h = blh & 1;
        return B + ((size_t)((b * 256 + n) * 16 + l)) * 384 + 128 + h * 64 + k0;
    } else if constexpr (MODE == 4) {
        return B + (size_t)blh * 16384 + (size_t)n * 256 + k0;
    } else {
        return B + (size_t)n * ldb + k0;
    }
}

__device__ __forceinline__ float gelu_exact(float v) {
    return 0.5f * v * (1.0f + erff(v * 0.70710678118654752f));
}

template<int MODE, int EPI, int NT>
__global__ void __launch_bounds__(256) mma_gemm(
        const float* __restrict__ A, const float* __restrict__ A2, int lda,
        const float* __restrict__ B, int ldb,
        const float* __restrict__ bias, float* __restrict__ C, int ldc, int K) {
    constexpr int MW = (NT == 128) ? 2 : 4;   // warps along M
    constexpr int NW = 8 / MW;                // warps along N
    constexpr int WM = 128 / MW;              // 64 or 32
    constexpr int WN = NT / NW;               // 32
    constexpr int MI = WM / 16;               // 4 or 2
    constexpr int NI = WN / 8;                // 4

    __shared__ __align__(16) uint32_t As[128][36];
    __shared__ __align__(16) uint32_t Bs[NT][36];
    __shared__ float sbias[NT];

    const int tid = threadIdx.x, wid = tid >> 5, lane = tid & 31;
    const int bm = blockIdx.y * 128, bn = blockIdx.x * NT;
    const int blh = blockIdx.z;
    const int wm0 = (wid & (MW - 1)) * WM;
    const int wn0 = (wid / MW) * WN;

    if (EPI == 0 || EPI == 1 || EPI == 2) {
        for (int i = tid; i < NT; i += 256) sbias[i] = bias[bn + i];
    }

    float acc[MI][NI][4];
#pragma unroll
    for (int mi = 0; mi < MI; mi++)
#pragma unroll
        for (int ni = 0; ni < NI; ni++)
#pragma unroll
            for (int q = 0; q < 4; q++) acc[mi][ni][q] = 0.f;

    for (int k0 = 0; k0 < K; k0 += 32) {
        // ---- stage A [128][32] ----
#pragma unroll
        for (int it = 0; it < 4; it++) {
            int row = it * 32 + (tid >> 3);
            const float* rp = a_ptr<MODE>(A, A2, lda, bm + row, k0, blh);
            float4 v = ((const float4*)rp)[tid & 7];
            uint4 u = make_uint4(f2tf32(v.x), f2tf32(v.y), f2tf32(v.z), f2tf32(v.w));
            *(uint4*)&As[row][(tid & 7) * 4] = u;
        }
        // ---- stage B [NT][32] ----
#pragma unroll
        for (int it = 0; it < NT / 32; it++) {
            int row = it * 32 + (tid >> 3);
            const float* rp = b_ptr<MODE>(B, ldb, bn + row, k0, blh);
            float4 v = ((const float4*)rp)[tid & 7];
            uint4 u = make_uint4(f2tf32(v.x), f2tf32(v.y), f2tf32(v.z), f2tf32(v.w));
            *(uint4*)&Bs[row][(tid & 7) * 4] = u;
        }
        __syncthreads();

#pragma unroll
        for (int ks = 0; ks < 4; ks++) {
            int kq = ks * 8 + (lane & 3);
            uint32_t afr[MI][4];
#pragma unroll
            for (int mi = 0; mi < MI; mi++) {
                int r = wm0 + mi * 16 + (lane >> 2);
                afr[mi][0] = As[r][kq];
                afr[mi][1] = As[r + 8][kq];
                afr[mi][2] = As[r][kq + 4];
                afr[mi][3] = As[r + 8][kq + 4];
            }
            uint32_t bfr[NI][2];
#pragma unroll
            for (int ni = 0; ni < NI; ni++) {
                int n = wn0 + ni * 8 + (lane >> 2);
                bfr[ni][0] = Bs[n][kq];
                bfr[ni][1] = Bs[n][kq + 4];
            }
#pragma unroll
            for (int mi = 0; mi < MI; mi++)
#pragma unroll
                for (int ni = 0; ni < NI; ni++)
                    mma_tf32(acc[mi][ni], afr[mi], bfr[ni]);
        }
        __syncthreads();
    }

    // ---- epilogue ----
#pragma unroll
    for (int mi = 0; mi < MI; mi++) {
#pragma unroll
        for (int ni = 0; ni < NI; ni++) {
#pragma unroll
            for (int half = 0; half < 2; half++) {
                int row = bm + wm0 + mi * 16 + (lane >> 2) + half * 8;
                int cl = wn0 + ni * 8 + 2 * (lane & 3);
                float f0 = acc[mi][ni][half * 2 + 0];
                float f1 = acc[mi][ni][half * 2 + 1];
                if constexpr (EPI == 0 || EPI == 2) { f0 += sbias[cl]; f1 += sbias[cl + 1]; }
                else if constexpr (EPI == 1) { f0 = gelu_exact(f0 + sbias[cl]); f1 = gelu_exact(f1 + sbias[cl + 1]); }
                else if constexpr (EPI == 3) { f0 *= 0.08838834764831843f; f1 *= 0.08838834764831843f; }
                float* cp;
                if constexpr (MODE == 4) {
                    int b = blh >> 5, l = (blh >> 1) & 15, h = blh & 1;
                    cp = C + ((size_t)((b * 256 + row) * 16 + l)) * 128 + h * 64 + cl;
                } else if constexpr (MODE == 3) {
                    cp = C + (size_t)blh * 65536 + (size_t)row * 256 + bn + cl;
                } else {
                    cp = C + (size_t)row * ldc + bn + cl;
                }
                float2 v = make_float2(f0, f1);
                if constexpr (EPI == 2 || EPI == 4) {
                    float2 o = *(float2*)cp;
                    v.x += o.x; v.y += o.y;
                }
                *(float2*)cp = v;
            }
        }
    }
}

// ===========================================================================
// attention 1: per window (16 tokens, 2 heads, hd=64). X += attn(V)
// ===========================================================================
__global__ void attn1_kernel(const float* __restrict__ QKV, float* __restrict__ X) {
    __shared__ float q[16][384];
    __shared__ float s[2][16][16];
    int w = blockIdx.x, tid = threadIdx.x;
    size_t base = (size_t)w * 16 * 384;
    for (int i = tid; i < 16 * 384; i += 128) q[i / 384][i % 384] = QKV[base + i];
    __syncthreads();
    for (int idx = tid; idx < 512; idx += 128) {
        int h = idx >> 8, t1 = (idx >> 4) & 15, t2 = idx & 15;
        const float* qp = &q[t1][h * 64];
        const float* kp = &q[t2][128 + h * 64];
        float a = 0.f;
#pragma unroll
        for (int c = 0; c < 64; c++) a = fmaf(qp[c], kp[c], a);
        s[h][t1][t2] = a * 0.08838834764831843f;
    }
    __syncthreads();
    if (tid < 32) {
        int h = tid >> 4, t1 = tid & 15;
        float m = -1e30f;
#pragma unroll
        for (int j = 0; j < 16; j++) m = fmaxf(m, s[h][t1][j]);
        float sum = 0.f;
#pragma unroll
        for (int j = 0; j < 16; j++) { float e = expf(s[h][t1][j] - m); s[h][t1][j] = e; sum += e; }
        float inv = 1.f / sum;
#pragma unroll
        for (int j = 0; j < 16; j++) s[h][t1][j] *= inv;
    }
    __syncthreads();
    for (int idx = tid; idx < 2048; idx += 128) {
        int t1 = idx >> 7, ch = idx & 127, h = ch >> 6;
        float a = 0.f;
#pragma unroll
        for (int j = 0; j < 16; j++) a = fmaf(s[h][t1][j], q[j][256 + ch], a);
        X[(size_t)(w * 16 + t1) * 128 + ch] += a;
    }
}

// ===========================================================================
// attn2 helpers: V transpose and row softmax of S
// ===========================================================================
__global__ void vt_kernel(const float* __restrict__ QKV, float* __restrict__ Vt) {
    __shared__ float t[32][65];
    int blh = blockIdx.x, g0 = blockIdx.y * 32;
    int b = blh >> 5, l = (blh >> 1) & 15, h = blh & 1;
    int tid = threadIdx.x;
#pragma unroll
    for (int it = 0; it < 8; it++) {
        int e = tid + it * 256;
        int g = e >> 6, c = e & 63;
        t[g][c] = QKV[((size_t)((b * 256 + g0 + g) * 16 + l)) * 384 + 256 + h * 64 + c];
    }
    __syncthreads();
    float* vp = Vt + (size_t)blh * 16384;
#pragma unroll
    for (int it = 0; it < 8; it++) {
        int e = tid + it * 256;
        int c = e >> 5, g = e & 31;
        vp[(size_t)c * 256 + g0 + g] = t[g][c];
    }
}

__global__ void softmax_s(float* __restrict__ S) {   // 131072 rows x 256
    int row = blockIdx.x * 8 + (threadIdx.x >> 5);
    int lane = threadIdx.x & 31;
    float* r = S + (size_t)row * 256;
    float v[8];
#pragma unroll
    for (int i = 0; i < 8; i++) v[i] = r[lane + i * 32];
    float m = -1e30f;
#pragma unroll
    for (int i = 0; i < 8; i++) m = fmaxf(m, v[i]);
#pragma unroll
    for (int o = 16; o; o >>= 1) m = fmaxf(m, __shfl_xor_sync(0xffffffffu, m, o));
    float s = 0.f;
#pragma unroll
    for (int i = 0; i < 8; i++) { v[i] = expf(v[i] - m); s += v[i]; }
#pragma unroll
    for (int o = 16; o; o >>= 1) s += __shfl_xor_sync(0xffffffffu, s, o);
    float inv = 1.f / s;
#pragma unroll
    for (int i = 0; i < 8; i++) r[lane + i * 32] = v[i] * inv;
}

// ===========================================================================
// reorder tokens -> pixel-major per sample
// ===========================================================================
__global__ void reorder_kernel(const float* __restrict__ X, float* __restrict__ Xr) {
    int idx = blockIdx.x * 256 + threadIdx.x;
    int n = idx >> 19;
    int r = idx & 524287;
    int p = r >> 7, ch = r & 127;
    int y = p >> 6, xx = p & 63;
    int yg = y >> 2, yl = y & 3, xg = xx >> 2, xl = xx & 3;
    int t = (n * 256 + yg * 16 + xg) * 16 + yl * 4 + xl;
    Xr[idx] = X[(size_t)t * 128 + ch];
}

// ===========================================================================
// LSTM pointwise
// ===========================================================================
__device__ __forceinline__ float softmax128(float v, float* red) {
    const unsigned FULL = 0xffffffffu;
    float m = v;
#pragma unroll
    for (int o = 16; o; o >>= 1) m = fmaxf(m, __shfl_xor_sync(FULL, m, o));
    if ((threadIdx.x & 31) == 0) red[threadIdx.x >> 5] = m;
    __syncthreads();
    m = fmaxf(fmaxf(red[0], red[1]), fmaxf(red[2], red[3]));
    __syncthreads();
    float e = expf(v - m), s = e;
#pragma unroll
    for (int o = 16; o; o >>= 1) s += __shfl_xor_sync(FULL, s, o);
    if ((threadIdx.x & 31) == 0) red[threadIdx.x >> 5] = s;
    __syncthreads();
    s = red[0] + red[1] + red[2] + red[3];
    __syncthreads();
    return e / s;
}

__global__ void lstm_point(const float* __restrict__ gates, float* __restrict__ h,
                           float* __restrict__ cst, float* __restrict__ out, int n) {
    __shared__ float red[4];
    int p = blockIdx.x, tid = threadIdx.x;
    float f  = gates[p * 512 + tid];
    float ig = gates[p * 512 + 128 + tid];
    float s  = gates[p * 512 + 256 + tid];
    float o  = gates[p * 512 + 384 + tid];
    f  = softmax128(f,  red);
    ig = softmax128(ig, red);
    o  = softmax128(o,  red);
    float cc = cst[p * 128 + tid];
    float cn = f * cc + ig * tanhf(s);
    float hn = o * tanhf(cn);
    cst[p * 128 + tid] = cn;
    h[p * 128 + tid]   = hn;
    out[((size_t)(n * 128 + tid)) * 4096 + p] = hn;
    if (n == 15) {
        out[((size_t)(16 * 128 + tid)) * 4096 + p] = hn;
        out[((size_t)(17 * 128 + tid)) * 4096 + p] = cn;
    }
}

// ===========================================================================
extern "C" void kernel_launch(void* const* d_in, const int* in_sizes, int n_in,
                              void* d_out, int out_size) {
    const float* x       = (const float*)d_in[0];
    const float* h0      = (const float*)d_in[1];
    const float* c0      = (const float*)d_in[2];
    const float* conv_w  = (const float*)d_in[3];
    const float* conv_b  = (const float*)d_in[4];
    const float* qkv1_w  = (const float*)d_in[5];
    const float* qkv1_b  = (const float*)d_in[6];
    const float* mlp1_w1 = (const float*)d_in[7];
    const float* mlp1_b1 = (const float*)d_in[8];
    const float* mlp1_w2 = (const float*)d_in[9];
    const float* mlp1_b2 = (const float*)d_in[10];
    const float* qkv2_w  = (const float*)d_in[11];
    const float* qkv2_b  = (const float*)d_in[12];
    const float* mlp2_w1 = (const float*)d_in[13];
    const float* mlp2_b1 = (const float*)d_in[14];
    const float* mlp2_w2 = (const float*)d_in[15];
    const float* mlp2_b2 = (const float*)d_in[16];
    const float* lstm_wx = (const float*)d_in[17];
    const float* lstm_wh = (const float*)d_in[18];
    const float* lstm_bh = (const float*)d_in[19];
    float* out = (float*)d_out;
    (void)in_sizes; (void)n_in; (void)out_size;

    float *X, *QKV, *Hid, *Xr, *Vt, *h, *c, *gates, *Wc, *Wl;
    cudaGetSymbolAddress((void**)&X, g_X);
    cudaGetSymbolAddress((void**)&QKV, g_QKV);
    cudaGetSymbolAddress((void**)&Hid, g_Hid);
    cudaGetSymbolAddress((void**)&Xr, g_Xr);
    cudaGetSymbolAddress((void**)&Vt, g_Vt);
    cudaGetSymbolAddress((void**)&h, g_h);
    cudaGetSymbolAddress((void**)&c, g_c);
    cudaGetSymbolAddress((void**)&gates, g_gates);
    cudaGetSymbolAddress((void**)&Wc, g_Wc);
    cudaGetSymbolAddress((void**)&Wl, g_Wl);

    prep_convw<<<512, 128>>>(conv_w, Wc);
    prep_lstmw<<<1024, 128>>>(lstm_wx, lstm_wh, Wl);
    init_hc<<<4096, 128>>>(h0, c0, h, c);
    transpose_x<<<32768, 256>>>(x, Hid);   // NHWC x lives in Hid (needs 33.5M floats!)

    // conv as implicit-im2col GEMM (reads NHWC x from Hid)
    mma_gemm<1, 0, 128><<<dim3(1, 512), 256>>>(Hid, nullptr, 0, Wc, 512, conv_b, X, 128, 512);

    // LocalMSA
    mma_gemm<0, 0, 128><<<dim3(3, 512), 256>>>(X, nullptr, 128, qkv1_w, 128, qkv1_b, QKV, 384, 128);
    attn1_kernel<<<NWIN, 128>>>(QKV, X);
    // MLP1 (Hid reused as hidden buffer; NHWC x no longer needed)
    mma_gemm<0, 1, 128><<<dim3(4, 512), 256>>>(X, nullptr, 128, mlp1_w1, 128, mlp1_b1, Hid, 512, 128);
    mma_gemm<0, 2, 128><<<dim3(1, 512), 256>>>(Hid, nullptr, 512, mlp1_w2, 512, mlp1_b2, X, 128, 512);

    // DilatedMSA
    mma_gemm<0, 0, 128><<<dim3(3, 512), 256>>>(X, nullptr, 128, qkv2_w, 128, qkv2_b, QKV, 384, 128);
    vt_kernel<<<dim3(512, 8), 256>>>(QKV, Vt);
    mma_gemm<3, 3, 128><<<dim3(2, 2, 512), 256>>>(QKV, nullptr, 0, QKV, 0, nullptr, Hid, 256, 64);
    softmax_s<<<16384, 256>>>(Hid);
    mma_gemm<4, 4, 64><<<dim3(1, 2, 512), 256>>>(Hid, nullptr, 256, Vt, 256, nullptr, X, 128, 256);
    // MLP2
    mma_gemm<0, 1, 128><<<dim3(4, 512), 256>>>(X, nullptr, 128, mlp2_w1, 128, mlp2_b1, Hid, 512, 128);
    mma_gemm<0, 2, 128><<<dim3(1, 512), 256>>>(Hid, nullptr, 512, mlp2_w2, 512, mlp2_b2, X, 128, 512);

    // window reverse
    reorder_kernel<<<32768, 256>>>(X, Xr);

    // ConvLSTM scan
    for (int n = 0; n < 16; n++) {
        mma_gemm<2, 0, 128><<<dim3(4, 32), 256>>>(Xr + (size_t)n * NPIX * 128, h, 128, Wl, 256, lstm_bh, gates, 512, 256);
        lstm_point<<<NPIX, 128>>>(gates, h, c, out, n);
    }
}